// round 2
// baseline (speedup 1.0000x reference)
#include <cuda_runtime.h>

// Problem constants (from reference): B=8192, N=4, C=4096
#define C_DIM   4096
#define N_DIM   4
#define THREADS 512
#define F4_PER_ROW (C_DIM / 4)      // 1024 float4 per (b,n) row
#define EPS 1e-6f

__global__ void __launch_bounds__(THREADS)
mhc_fused_kernel(const float* __restrict__ x,
                 const float* __restrict__ H_pre,
                 const float* __restrict__ H_post,
                 const float* __restrict__ H_res,
                 const float* __restrict__ w,
                 float* __restrict__ out)
{
    const int b = blockIdx.x;
    const int t = threadIdx.x;

    // ---- uniform scalar prep (redundant per thread; trivial cost) ----
    float pre[N_DIM], post[N_DIM], P[N_DIM][N_DIM];
#pragma unroll
    for (int n = 0; n < N_DIM; n++) {
        pre[n]  = 1.0f / (1.0f + expf(-H_pre[n]));
        post[n] = 2.0f / (1.0f + expf(-H_post[n]));
    }
#pragma unroll
    for (int i = 0; i < N_DIM; i++)
#pragma unroll
        for (int j = 0; j < N_DIM; j++)
            P[i][j] = expf(H_res[i * N_DIM + j]);

#pragma unroll
    for (int it = 0; it < 3; it++) {
        // row normalize
#pragma unroll
        for (int i = 0; i < N_DIM; i++) {
            float s = P[i][0] + P[i][1] + P[i][2] + P[i][3] + EPS;
            float inv = 1.0f / s;
#pragma unroll
            for (int j = 0; j < N_DIM; j++) P[i][j] *= inv;
        }
        // col normalize
#pragma unroll
        for (int j = 0; j < N_DIM; j++) {
            float s = P[0][j] + P[1][j] + P[2][j] + P[3][j] + EPS;
            float inv = 1.0f / s;
#pragma unroll
            for (int i = 0; i < N_DIM; i++) P[i][j] *= inv;
        }
    }

    // ---- load this batch row's 4 streams (each thread: 2 float4 per stream) ----
    const float4* x4 = reinterpret_cast<const float4*>(x) +
                       (size_t)b * N_DIM * F4_PER_ROW;

    float4 v[N_DIM][2];
#pragma unroll
    for (int n = 0; n < N_DIM; n++) {
        v[n][0] = x4[n * F4_PER_ROW + t];
        v[n][1] = x4[n * F4_PER_ROW + t + THREADS];
    }

    // ---- aggregate: x_agg = sum_n pre[n] * x[b,n,:] ----
    float4 agg[2];
#pragma unroll
    for (int j = 0; j < 2; j++) {
        agg[j].x = pre[0]*v[0][j].x + pre[1]*v[1][j].x + pre[2]*v[2][j].x + pre[3]*v[3][j].x;
        agg[j].y = pre[0]*v[0][j].y + pre[1]*v[1][j].y + pre[2]*v[2][j].y + pre[3]*v[3][j].y;
        agg[j].z = pre[0]*v[0][j].z + pre[1]*v[1][j].z + pre[2]*v[2][j].z + pre[3]*v[3][j].z;
        agg[j].w = pre[0]*v[0][j].w + pre[1]*v[1][j].w + pre[2]*v[2][j].w + pre[3]*v[3][j].w;
    }

    // ---- block reduction of sum(agg^2) over C ----
    float ss = agg[0].x*agg[0].x + agg[0].y*agg[0].y + agg[0].z*agg[0].z + agg[0].w*agg[0].w
             + agg[1].x*agg[1].x + agg[1].y*agg[1].y + agg[1].z*agg[1].z + agg[1].w*agg[1].w;

#pragma unroll
    for (int o = 16; o > 0; o >>= 1)
        ss += __shfl_xor_sync(0xffffffffu, ss, o);

    __shared__ float sred[17];
    if ((t & 31) == 0) sred[t >> 5] = ss;
    __syncthreads();
    if (t < 16) {
        float s = sred[t];
#pragma unroll
        for (int o = 8; o > 0; o >>= 1)
            s += __shfl_xor_sync(0x0000ffffu, s, o, 16);
        if (t == 0) sred[16] = s;
    }
    __syncthreads();

    const float mean = sred[16] * (1.0f / (float)C_DIM);
    const float rinv = rsqrtf(mean + EPS);

    // ---- y_norm = agg * rinv * weight ----
    const float4* w4 = reinterpret_cast<const float4*>(w);
    float4 wv0 = w4[t];
    float4 wv1 = w4[t + THREADS];

    float4 yn[2];
    yn[0].x = agg[0].x * rinv * wv0.x;
    yn[0].y = agg[0].y * rinv * wv0.y;
    yn[0].z = agg[0].z * rinv * wv0.z;
    yn[0].w = agg[0].w * rinv * wv0.w;
    yn[1].x = agg[1].x * rinv * wv1.x;
    yn[1].y = agg[1].y * rinv * wv1.y;
    yn[1].z = agg[1].z * rinv * wv1.z;
    yn[1].w = agg[1].w * rinv * wv1.w;

    // ---- out[b,m,:] = sum_n P[m][n]*x[b,n,:] + post[m]*y_norm ----
    float4* o4 = reinterpret_cast<float4*>(out) + (size_t)b * N_DIM * F4_PER_ROW;

#pragma unroll
    for (int m = 0; m < N_DIM; m++) {
#pragma unroll
        for (int j = 0; j < 2; j++) {
            float4 o;
            o.x = P[m][0]*v[0][j].x + P[m][1]*v[1][j].x + P[m][2]*v[2][j].x + P[m][3]*v[3][j].x
                + post[m]*yn[j].x;
            o.y = P[m][0]*v[0][j].y + P[m][1]*v[1][j].y + P[m][2]*v[2][j].y + P[m][3]*v[3][j].y
                + post[m]*yn[j].y;
            o.z = P[m][0]*v[0][j].z + P[m][1]*v[1][j].z + P[m][2]*v[2][j].z + P[m][3]*v[3][j].z
                + post[m]*yn[j].z;
            o.w = P[m][0]*v[0][j].w + P[m][1]*v[1][j].w + P[m][2]*v[2][j].w + P[m][3]*v[3][j].w
                + post[m]*yn[j].w;
            o4[m * F4_PER_ROW + t + j * THREADS] = o;
        }
    }
}

extern "C" void kernel_launch(void* const* d_in, const int* in_sizes, int n_in,
                              void* d_out, int out_size)
{
    const float* x      = (const float*)d_in[0];   // [8192, 4, 4096]
    const float* H_pre  = (const float*)d_in[1];   // [4]
    const float* H_post = (const float*)d_in[2];   // [4]
    const float* H_res  = (const float*)d_in[3];   // [4, 4]
    const float* w      = (const float*)d_in[4];   // [4096]
    float* out          = (float*)d_out;           // [8192, 4, 4096]

    const int B = in_sizes[0] / (N_DIM * C_DIM);   // 8192

    mhc_fused_kernel<<<B, THREADS>>>(x, H_pre, H_post, H_res, w, out);
}